// round 13
// baseline (speedup 1.0000x reference)
#include <cuda_runtime.h>
#include <cuda_bf16.h>

// Depth-2 signature, Levy-area wedge pairing + bulk-async staging (raw 72B rows):
//   A = sum_s (x(2s)-x(2s+2)) ^ x(2s+1)   (rows >= 1000 treated as zero)
//   S2 = 0.5*A + 0.5*(xT xT^T - x0 x0^T) - x0 (xT - x0)^T,  S1 = xT - x0
// Time channel analytic:  P[0][j] = -(2/999)SV_j + (1000/999)x999_j
//                         P[j][0] = (1/999)(x0_j + 2*SE_j)   (Abel summation)
// R13: (a) V via ONE LDS.128 at 16B-aligned shifted slice (cols 4bj-2..4bj+1,
//          junk cols wrap to 18/19 and are discarded in the epilogue)
//      (b) 3-stage TMA pipeline (3 buffers / 3 mbarriers, copy issued 2 ahead)

#define THREADS 256
#define TROW    18
#define SEQLEN  18000
#define NTILE   8
#define TILEB   9296          // bytes per full tile copy (129 rows * 72B, padded to 16)
#define LASTB   7488          // tile 7: rows 896..999 exactly
#define BUFF    2336          // floats per buffer (9344 B)
#define ZSTART  1872          // first zero float of buffer-1 tail

__device__ __forceinline__ unsigned long long pk2(float lo, float hi) {
    unsigned long long r;
    asm("mov.b64 %0, {%1,%2};" : "=l"(r) : "f"(lo), "f"(hi));
    return r;
}
__device__ __forceinline__ void up2(unsigned long long v, float& lo, float& hi) {
    asm("mov.b64 {%0,%1}, %2;" : "=f"(lo), "=f"(hi) : "l"(v));
}
__device__ __forceinline__ void ffma2(unsigned long long& a, unsigned long long x,
                                      unsigned long long y) {
    asm("fma.rn.f32x2 %0, %1, %2, %0;" : "+l"(a) : "l"(x), "l"(y));
}
__device__ __forceinline__ void addf2(unsigned long long& a, unsigned long long x) {
    asm("add.rn.f32x2 %0, %0, %1;" : "+l"(a) : "l"(x));
}
__device__ __forceinline__ void mbar_init(unsigned mb, unsigned cnt) {
    asm volatile("mbarrier.init.shared.b64 [%0], %1;" :: "r"(mb), "r"(cnt) : "memory");
}
__device__ __forceinline__ void mbar_expect_tx(unsigned mb, unsigned bytes) {
    asm volatile("mbarrier.arrive.expect_tx.shared.b64 _, [%0], %1;"
                 :: "r"(mb), "r"(bytes) : "memory");
}
__device__ __forceinline__ void bulk_g2s(unsigned dst, const void* src,
                                         unsigned bytes, unsigned mb) {
    asm volatile("cp.async.bulk.shared::cluster.global.mbarrier::complete_tx::bytes "
                 "[%0], [%1], %2, [%3];"
                 :: "r"(dst), "l"(src), "r"(bytes), "r"(mb) : "memory");
}
__device__ __forceinline__ void mbar_wait(unsigned mb, unsigned parity) {
    unsigned done;
    asm volatile(
        "{\n\t.reg .pred p;\n\t"
        "mbarrier.try_wait.parity.acquire.cta.shared::cta.b64 p, [%1], %2;\n\t"
        "selp.b32 %0, 1, 0, p;\n\t}"
        : "=r"(done) : "r"(mb), "r"(parity) : "memory");
    if (!done) {
        asm volatile(
            "{\n\t.reg .pred P1;\n\t"
            "WL_%=:\n\t"
            "mbarrier.try_wait.parity.acquire.cta.shared::cta.b64 P1, [%0], %1, 0x989680;\n\t"
            "@P1 bra.uni WD_%=;\n\t"
            "bra.uni WL_%=;\n\t"
            "WD_%=:\n\t}"
            :: "r"(mb), "r"(parity) : "memory");
    }
}

__global__ __launch_bounds__(THREADS, 4)
void sig2_kernel(const float* __restrict__ x, float* __restrict__ out) {
    const int n = blockIdx.x;
    const float* __restrict__ Xn = x + (size_t)n * SEQLEN;

    __shared__ __align__(16) float xs[3 * BUFF];     // 28.0 KB
    __shared__ float x0_s[20], xT_s[20];
    __shared__ __align__(8) unsigned long long mbar[3];

    const int tid  = threadIdx.x;
    const int w    = tid >> 5;
    const int lane = tid & 31;
    const float INV = 1.0f / 999.0f;

    if (tid < 18) { x0_s[tid + 1] = Xn[tid]; xT_s[tid + 1] = Xn[999 * TROW + tid]; }
    if (tid == 18) { x0_s[0] = 0.0f; xT_s[0] = 1.0f; }

    unsigned mba[3], sba[3];
#pragma unroll
    for (int b = 0; b < 3; ++b) {
        mba[b] = (unsigned)__cvta_generic_to_shared(&mbar[b]);
        sba[b] = (unsigned)__cvta_generic_to_shared(xs + b * BUFF);
    }

    if (tid == 0) { mbar_init(mba[0], 1); mbar_init(mba[1], 1); mbar_init(mba[2], 1); }
    __syncthreads();

    if (tid == 0) {
        mbar_expect_tx(mba[0], TILEB); bulk_g2s(sba[0], Xn, TILEB, mba[0]);
        mbar_expect_tx(mba[1], TILEB); bulk_g2s(sba[1], Xn + 2304, TILEB, mba[1]);
    }

    const bool mact = (lane < 25);
    const int bi = lane / 5;
    const int bj = lane - 5 * bi;
    const bool do_sv = mact && (bi == 0);   // v-column sums (shifted cols)
    const bool do_se = mact && (bj == 0);   // even-row sums (Abel)

    unsigned long long acc[4][2];
#pragma unroll
    for (int i = 0; i < 4; ++i) { acc[i][0] = 0ull; acc[i][1] = 0ull; }
    unsigned long long sv01 = 0ull, sv23 = 0ull;
    unsigned long long se01 = 0ull, se23 = 0ull;

    for (int t = 0; t < NTILE; ++t) {
        const int nt = t + 2;
        if (tid == 0 && nt < NTILE) {
            const unsigned bytes = (nt == NTILE - 1) ? LASTB : TILEB;
            const int b = nt % 3;
            mbar_expect_tx(mba[b], bytes);
            bulk_g2s(sba[b], Xn + nt * 2304, bytes, mba[b]);
        }
        if (t == 5) {   // zero tail of buffer 1 (rows >= 1000) before tile 7 is consumed
            for (int i = tid; i < BUFF - ZSTART; i += THREADS) xs[BUFF + ZSTART + i] = 0.0f;
        }

        mbar_wait(mba[t % 3], (t / 3) & 1);

        if (mact) {
            const float* bb = xs + (t % 3) * BUFF;
            const float* Ep = bb + 288 * w + 4 * bi;        // even rows, 16B aligned
            const float* Vp = bb + 288 * w + 16 + 4 * bj;   // odd rows shifted -2, 16B aligned
            float4 Ec = *(const float4*)Ep;
#pragma unroll
            for (int k = 0; k < 8; ++k) {
                const float4 En = *(const float4*)(Ep + 36 * (k + 1));
                const ulonglong2 vv = *(const ulonglong2*)(Vp + 36 * k);
                const float u0 = Ec.x - En.x, u1 = Ec.y - En.y;
                const float u2 = Ec.z - En.z, u3 = Ec.w - En.w;
                unsigned long long mm;
                mm = pk2(u0, u0); ffma2(acc[0][0], mm, vv.x); ffma2(acc[0][1], mm, vv.y);
                mm = pk2(u1, u1); ffma2(acc[1][0], mm, vv.x); ffma2(acc[1][1], mm, vv.y);
                mm = pk2(u2, u2); ffma2(acc[2][0], mm, vv.x); ffma2(acc[2][1], mm, vv.y);
                mm = pk2(u3, u3); ffma2(acc[3][0], mm, vv.x); ffma2(acc[3][1], mm, vv.y);
                if (do_sv) { addf2(sv01, vv.x); addf2(sv23, vv.y); }
                if (do_se) { addf2(se01, pk2(En.x, En.y)); addf2(se23, pk2(En.z, En.w)); }
                Ec = En;
            }
        }
        __syncthreads();
    }

    // ---- reduction: 8 warp-partials (20x20 P tile + sv[20] + SE[20]) ----
    // lane (bi,bj) holds P rows 4bi..4bi+3, cols 4bj-2..4bj+1 (wrap negatives -> 18/19)
    float* red = xs;                 // 8*440 = 3520 floats
    float* Ps  = xs + 3520;          // 440 floats (total 3960 <= 7008)

    const int c0 = 4 * bj - 2;
    const int cw0 = (c0 + 20) % 20;          // wrapped col for e=0
    const int cw1 = (c0 + 21) % 20;          // wrapped col for e=1
    if (mact) {
#pragma unroll
        for (int ii = 0; ii < 4; ++ii) {
            float a, b, c, d;
            up2(acc[ii][0], a, b);
            up2(acc[ii][1], c, d);
            const int rb = w * 440 + (4 * bi + ii) * 20;
            red[rb + cw0] = a; red[rb + cw1] = b;
            red[rb + c0 + 2] = c; red[rb + c0 + 3] = d;
        }
    }
    if (do_sv) {
        float a, b, c, d;
        up2(sv01, a, b);
        up2(sv23, c, d);
        const int rb = w * 440 + 400;
        red[rb + cw0] = a; red[rb + cw1] = b;
        red[rb + c0 + 2] = c; red[rb + c0 + 3] = d;
    }
    if (do_se) {
        float a, b, c, d;
        up2(se01, a, b);
        up2(se23, c, d);
        const int rb = w * 440 + 420 + 4 * bi;
        red[rb] = a; red[rb + 1] = b; red[rb + 2] = c; red[rb + 3] = d;
    }
    __syncthreads();

    for (int p = tid; p < 440; p += THREADS) {
        Ps[p] = red[p]         + red[p + 440]  + red[p + 880]  + red[p + 1320]
              + red[p + 1760]  + red[p + 2200] + red[p + 2640] + red[p + 3080];
    }
    __syncthreads();

    const float* SV = Ps + 400;
    const float* SE = Ps + 420;

    // ---- epilogue: A = P - P^T (data block + analytic time row/col) ----
    float* o = out + (size_t)n * 380;
    for (int pp = tid; pp < 361; pp += THREADS) {
        const int fi = pp / 19;
        const int fj = pp - 19 * fi;
        float A;
        if (fi > 0 && fj > 0) {
            A = Ps[(fi - 1) * 20 + (fj - 1)] - Ps[(fj - 1) * 20 + (fi - 1)];
        } else if (fi == 0 && fj == 0) {
            A = 0.0f;
        } else if (fi == 0) {
            const int c = fj - 1;
            const float P0j = -2.0f * INV * SV[c] + 1000.0f * INV * xT_s[fj];
            const float Pj0 = INV * (x0_s[fj] + 2.0f * SE[c]);   // Abel
            A = P0j - Pj0;
        } else {
            const int c = fi - 1;
            const float P0i = -2.0f * INV * SV[c] + 1000.0f * INV * xT_s[fi];
            const float Pi0 = INV * (x0_s[fi] + 2.0f * SE[c]);   // Abel
            A = Pi0 - P0i;
        }
        o[19 + pp] = 0.5f * A
                   + 0.5f * (xT_s[fi] * xT_s[fj] - x0_s[fi] * x0_s[fj])
                   - x0_s[fi] * (xT_s[fj] - x0_s[fj]);
    }
    if (tid < 19) o[tid] = xT_s[tid] - x0_s[tid];   // S1
}

extern "C" void kernel_launch(void* const* d_in, const int* in_sizes, int n_in,
                              void* d_out, int out_size) {
    const float* x = (const float*)d_in[0];
    float* out = (float*)d_out;
    sig2_kernel<<<2048, THREADS>>>(x, out);
}

// round 14
// speedup vs baseline: 1.0767x; 1.0767x over previous
#include <cuda_runtime.h>
#include <cuda_bf16.h>

// Depth-2 signature, Levy-area wedge pairing + bulk-async staging (raw 72B rows):
//   A = sum_s (x(2s)-x(2s+2)) ^ x(2s+1)   (rows >= 1000 treated as zero)
//   S2 = 0.5*A + 0.5*(xT xT^T - x0 x0^T) - x0 (xT - x0)^T,  S1 = xT - x0
// Time channel analytic:  P[0][j] = -(2/999)SV_j + (1000/999)x999_j
//                         P[j][0] = (1/999)(x0_j + 2*SE_j)   (Abel summation)
// R14: R12 base (2-stage pipeline, lb(256,4)) with TRANSPOSED packing:
//   acc pairs pack ROWS (u01,u23 from packed subs); v duplicated instead of u;
//   se accumulates packed En directly (no pk2).

#define THREADS 256
#define TROW    18
#define SEQLEN  18000
#define NTILE   8
#define TILEB   9296          // bytes per full tile copy (129 rows * 72B, padded to 16)
#define LASTB   7488          // tile 7: rows 896..999 exactly
#define BUFF    2336          // floats per buffer (9344 B)
#define ZSTART  1872          // first zero float of buffer-1 tail

__device__ __forceinline__ unsigned long long pk2(float lo, float hi) {
    unsigned long long r;
    asm("mov.b64 %0, {%1,%2};" : "=l"(r) : "f"(lo), "f"(hi));
    return r;
}
__device__ __forceinline__ void up2(unsigned long long v, float& lo, float& hi) {
    asm("mov.b64 {%0,%1}, %2;" : "=f"(lo), "=f"(hi) : "l"(v));
}
__device__ __forceinline__ void ffma2(unsigned long long& a, unsigned long long x,
                                      unsigned long long y) {
    asm("fma.rn.f32x2 %0, %1, %2, %0;" : "+l"(a) : "l"(x), "l"(y));
}
__device__ __forceinline__ void addf2(unsigned long long& a, unsigned long long x) {
    asm("add.rn.f32x2 %0, %0, %1;" : "+l"(a) : "l"(x));
}
__device__ __forceinline__ unsigned long long subf2(unsigned long long a,
                                                    unsigned long long b) {
    unsigned long long r;
    asm("sub.rn.f32x2 %0, %1, %2;" : "=l"(r) : "l"(a), "l"(b));
    return r;
}
__device__ __forceinline__ void mbar_init(unsigned mb, unsigned cnt) {
    asm volatile("mbarrier.init.shared.b64 [%0], %1;" :: "r"(mb), "r"(cnt) : "memory");
}
__device__ __forceinline__ void mbar_expect_tx(unsigned mb, unsigned bytes) {
    asm volatile("mbarrier.arrive.expect_tx.shared.b64 _, [%0], %1;"
                 :: "r"(mb), "r"(bytes) : "memory");
}
__device__ __forceinline__ void bulk_g2s(unsigned dst, const void* src,
                                         unsigned bytes, unsigned mb) {
    asm volatile("cp.async.bulk.shared::cluster.global.mbarrier::complete_tx::bytes "
                 "[%0], [%1], %2, [%3];"
                 :: "r"(dst), "l"(src), "r"(bytes), "r"(mb) : "memory");
}
__device__ __forceinline__ void mbar_wait(unsigned mb, unsigned parity) {
    unsigned done;
    asm volatile(
        "{\n\t.reg .pred p;\n\t"
        "mbarrier.try_wait.parity.acquire.cta.shared::cta.b64 p, [%1], %2;\n\t"
        "selp.b32 %0, 1, 0, p;\n\t}"
        : "=r"(done) : "r"(mb), "r"(parity) : "memory");
    if (!done) {
        asm volatile(
            "{\n\t.reg .pred P1;\n\t"
            "WL_%=:\n\t"
            "mbarrier.try_wait.parity.acquire.cta.shared::cta.b64 P1, [%0], %1, 0x989680;\n\t"
            "@P1 bra.uni WD_%=;\n\t"
            "bra.uni WL_%=;\n\t"
            "WD_%=:\n\t}"
            :: "r"(mb), "r"(parity) : "memory");
    }
}

__global__ __launch_bounds__(THREADS, 4)
void sig2_kernel(const float* __restrict__ x, float* __restrict__ out) {
    const int n = blockIdx.x;
    const float* __restrict__ Xn = x + (size_t)n * SEQLEN;

    __shared__ __align__(16) float xs[2 * BUFF];     // 18.7 KB
    __shared__ float x0_s[20], xT_s[20];
    __shared__ __align__(8) unsigned long long mbar[2];

    const int tid  = threadIdx.x;
    const int w    = tid >> 5;
    const int lane = tid & 31;
    const float INV = 1.0f / 999.0f;

    if (tid < 18) { x0_s[tid + 1] = Xn[tid]; xT_s[tid + 1] = Xn[999 * TROW + tid]; }
    if (tid == 18) { x0_s[0] = 0.0f; xT_s[0] = 1.0f; }

    const unsigned mb0 = (unsigned)__cvta_generic_to_shared(&mbar[0]);
    const unsigned mb1 = (unsigned)__cvta_generic_to_shared(&mbar[1]);
    const unsigned sb0 = (unsigned)__cvta_generic_to_shared(xs);
    const unsigned sb1 = (unsigned)__cvta_generic_to_shared(xs + BUFF);

    if (tid == 0) { mbar_init(mb0, 1); mbar_init(mb1, 1); }
    __syncthreads();

    if (tid == 0) { mbar_expect_tx(mb0, TILEB); bulk_g2s(sb0, Xn, TILEB, mb0); }

    const bool mact = (lane < 25);
    const int bi = lane / 5;
    const int bj = lane - 5 * bi;
    const bool do_sv = mact && (bi == 0);   // v-column sums
    const bool do_se = mact && (bj == 0);   // even-row sums (Abel)

    // accT[j][q]: packed pair (P[4bi+2q][4bj+j], P[4bi+2q+1][4bj+j])
    unsigned long long accT[4][2];
#pragma unroll
    for (int i = 0; i < 4; ++i) { accT[i][0] = 0ull; accT[i][1] = 0ull; }
    unsigned long long sv01 = 0ull, sv23 = 0ull;
    unsigned long long se01 = 0ull, se23 = 0ull;

    for (int t = 0; t < NTILE; ++t) {
        const int nt = t + 1;
        if (tid == 0 && nt < NTILE) {
            const unsigned bytes = (nt == NTILE - 1) ? LASTB : TILEB;
            const unsigned mb = (nt & 1) ? mb1 : mb0;
            const unsigned db = (nt & 1) ? sb1 : sb0;
            mbar_expect_tx(mb, bytes);
            bulk_g2s(db, Xn + nt * 2304, bytes, mb);
        }
        if (t == 6) {   // zero tail of buffer 1 (rows >= 1000) before tile 7 is consumed
            for (int i = tid; i < BUFF - ZSTART; i += THREADS) xs[BUFF + ZSTART + i] = 0.0f;
        }

        mbar_wait((t & 1) ? mb1 : mb0, (t >> 1) & 1);

        if (mact) {
            const float* bb = xs + (t & 1) * BUFF;
            const float* Ep = bb + 288 * w + 4 * bi;        // even rows, 16B aligned
            const float* Vp = bb + 288 * w + 18 + 4 * bj;   // odd rows, 8B aligned
            ulonglong2 Ec = *(const ulonglong2*)Ep;          // packed (e0,e1),(e2,e3)
#pragma unroll
            for (int k = 0; k < 8; ++k) {
                const ulonglong2 En = *(const ulonglong2*)(Ep + 36 * (k + 1));
                const float2 Va = *(const float2*)(Vp + 36 * k);
                const float2 Vb = *(const float2*)(Vp + 36 * k + 2);
                const unsigned long long u01 = subf2(Ec.x, En.x);
                const unsigned long long u23 = subf2(Ec.y, En.y);
                unsigned long long mj;
                mj = pk2(Va.x, Va.x); ffma2(accT[0][0], u01, mj); ffma2(accT[0][1], u23, mj);
                mj = pk2(Va.y, Va.y); ffma2(accT[1][0], u01, mj); ffma2(accT[1][1], u23, mj);
                mj = pk2(Vb.x, Vb.x); ffma2(accT[2][0], u01, mj); ffma2(accT[2][1], u23, mj);
                mj = pk2(Vb.y, Vb.y); ffma2(accT[3][0], u01, mj); ffma2(accT[3][1], u23, mj);
                if (do_sv) { addf2(sv01, pk2(Va.x, Va.y)); addf2(sv23, pk2(Vb.x, Vb.y)); }
                if (do_se) { addf2(se01, En.x); addf2(se23, En.y); }
                Ec = En;
            }
        }
        __syncthreads();
    }

    // ---- reduction: 8 warp-partials (20x20 P tile + sv[20] + SE[20]) ----
    float* red = xs;                 // 8*440 = 3520 floats
    float* Ps  = xs + 3520;          // 440 floats (total 3960 <= 4672)

    if (mact) {
#pragma unroll
        for (int jj = 0; jj < 4; ++jj) {
#pragma unroll
            for (int q = 0; q < 2; ++q) {
                float lo, hi;
                up2(accT[jj][q], lo, hi);
                const int col = 4 * bj + jj;
                red[w * 440 + (4 * bi + 2 * q) * 20 + col]     = lo;
                red[w * 440 + (4 * bi + 2 * q + 1) * 20 + col] = hi;
            }
        }
    }
    if (do_sv) {
        float a, b, c, d;
        up2(sv01, a, b);
        up2(sv23, c, d);
        const int base = w * 440 + 400 + 4 * bj;
        red[base] = a; red[base + 1] = b; red[base + 2] = c; red[base + 3] = d;
    }
    if (do_se) {
        float a, b, c, d;
        up2(se01, a, b);
        up2(se23, c, d);
        const int base = w * 440 + 420 + 4 * bi;
        red[base] = a; red[base + 1] = b; red[base + 2] = c; red[base + 3] = d;
    }
    __syncthreads();

    for (int p = tid; p < 440; p += THREADS) {
        Ps[p] = red[p]         + red[p + 440]  + red[p + 880]  + red[p + 1320]
              + red[p + 1760]  + red[p + 2200] + red[p + 2640] + red[p + 3080];
    }
    __syncthreads();

    const float* SV = Ps + 400;
    const float* SE = Ps + 420;

    // ---- epilogue: A = P - P^T (data block + analytic time row/col) ----
    float* o = out + (size_t)n * 380;
    for (int pp = tid; pp < 361; pp += THREADS) {
        const int fi = pp / 19;
        const int fj = pp - 19 * fi;
        float A;
        if (fi > 0 && fj > 0) {
            A = Ps[(fi - 1) * 20 + (fj - 1)] - Ps[(fj - 1) * 20 + (fi - 1)];
        } else if (fi == 0 && fj == 0) {
            A = 0.0f;
        } else if (fi == 0) {
            const int c = fj - 1;
            const float P0j = -2.0f * INV * SV[c] + 1000.0f * INV * xT_s[fj];
            const float Pj0 = INV * (x0_s[fj] + 2.0f * SE[c]);   // Abel
            A = P0j - Pj0;
        } else {
            const int c = fi - 1;
            const float P0i = -2.0f * INV * SV[c] + 1000.0f * INV * xT_s[fi];
            const float Pi0 = INV * (x0_s[fi] + 2.0f * SE[c]);   // Abel
            A = Pi0 - P0i;
        }
        o[19 + pp] = 0.5f * A
                   + 0.5f * (xT_s[fi] * xT_s[fj] - x0_s[fi] * x0_s[fj])
                   - x0_s[fi] * (xT_s[fj] - x0_s[fj]);
    }
    if (tid < 19) o[tid] = xT_s[tid] - x0_s[tid];   // S1
}

extern "C" void kernel_launch(void* const* d_in, const int* in_sizes, int n_in,
                              void* d_out, int out_size) {
    const float* x = (const float*)d_in[0];
    float* out = (float*)d_out;
    sig2_kernel<<<2048, THREADS>>>(x, out);
}